// round 13
// baseline (speedup 1.0000x reference)
#include <cuda_runtime.h>
#include <cuda_bf16.h>
#include <math.h>
#include <stdint.h>

#define BATCH 8192
#define NB    11
#define PERF  12
#define BN_EPS 1e-5f

// ---------------- static scratch (no runtime allocation) --------------------
// ping-pong expanded activations (8192 x 6144 bf16 each)
static __device__ __align__(128) __nv_bfloat16 g_Eh0[BATCH * 6144];
static __device__ __align__(128) __nv_bfloat16 g_El0[BATCH * 6144];
static __device__ __align__(128) __nv_bfloat16 g_Eh1[BATCH * 6144];
static __device__ __align__(128) __nv_bfloat16 g_El1[BATCH * 6144];
static __device__ __align__(128) __nv_bfloat16 g_Wh0[3072 * 512];
static __device__ __align__(128) __nv_bfloat16 g_Wl0[3072 * 512];
static __device__ __align__(128) __nv_bfloat16 g_Wh1[6144 * 512];
static __device__ __align__(128) __nv_bfloat16 g_Wl1[6144 * 512];
static __device__ __align__(128) __nv_bfloat16 g_Wh2[6144 * 256];
static __device__ __align__(128) __nv_bfloat16 g_Wl2[6144 * 256];

// ---------------- PTX helpers (family-target safe: sm_80+ ISA only) ---------
__device__ __forceinline__ uint32_t smem_u32(const void* p) {
    uint32_t a;
    asm("{ .reg .u64 t; cvta.to.shared.u64 t, %1; cvt.u32.u64 %0, t; }" : "=r"(a) : "l"(p));
    return a;
}
__device__ __forceinline__ void ldsm4(uint32_t* r, uint32_t addr) {
    asm volatile("ldmatrix.sync.aligned.m8n8.x4.shared.b16 {%0,%1,%2,%3}, [%4];"
                 : "=r"(r[0]), "=r"(r[1]), "=r"(r[2]), "=r"(r[3]) : "r"(addr));
}
__device__ __forceinline__ void mma16816(float* d, const uint32_t* a, const uint32_t* b) {
    asm volatile("mma.sync.aligned.m16n8k16.row.col.f32.bf16.bf16.f32 "
                 "{%0,%1,%2,%3}, {%4,%5,%6,%7}, {%8,%9}, {%0,%1,%2,%3};"
                 : "+f"(d[0]), "+f"(d[1]), "+f"(d[2]), "+f"(d[3])
                 : "r"(a[0]), "r"(a[1]), "r"(a[2]), "r"(a[3]), "r"(b[0]), "r"(b[1]));
}
__device__ __forceinline__ void cp16(uint32_t dst, const void* src) {
    asm volatile("cp.async.cg.shared.global [%0], [%1], 16;" :: "r"(dst), "l"(src));
}
__device__ __forceinline__ void cp_commit() { asm volatile("cp.async.commit_group;" ::: "memory"); }
template <int W> __device__ __forceinline__ void cp_wait() {
    asm volatile("cp.async.wait_group %0;" :: "n"(W) : "memory");
}

// packed hi/lo quantization: 2 values -> 1 bf16x2 hi word + 1 bf16x2 lo word
__device__ __forceinline__ void quant_pair(float v0, float v1, uint32_t& ph, uint32_t& pl) {
    uint32_t h;
    asm("cvt.rn.bf16x2.f32 %0, %1, %2;" : "=r"(h) : "f"(v1), "f"(v0));
    float h0 = __uint_as_float(h << 16);
    float h1 = __uint_as_float(h & 0xFFFF0000u);
    uint32_t l;
    float l0 = v0 - h0, l1 = v1 - h1;
    asm("cvt.rn.bf16x2.f32 %0, %1, %2;" : "=r"(l) : "f"(l1), "f"(l0));
    ph = h; pl = l;
}

__device__ __forceinline__ void store12(const float* v, __nv_bfloat16* dsth, __nv_bfloat16* dstl) {
    uint32_t ph[6], pl[6];
#pragma unroll
    for (int p = 0; p < 6; p++) quant_pair(v[2 * p], v[2 * p + 1], ph[p], pl[p]);
    uint2* dh = (uint2*)dsth;
    uint2* dl = (uint2*)dstl;
    dh[0] = make_uint2(ph[0], ph[1]); dh[1] = make_uint2(ph[2], ph[3]); dh[2] = make_uint2(ph[4], ph[5]);
    dl[0] = make_uint2(pl[0], pl[1]); dl[1] = make_uint2(pl[2], pl[3]); dl[2] = make_uint2(pl[4], pl[5]);
}

// ---------------- expansion core (closed-form uniform cubic B-splines) ------
__device__ __forceinline__ void expand_value(float xv, __nv_bfloat16* dsth, __nv_bfloat16* dstl) {
    float t  = (xv + 1.75f) * 4.0f;
    float fm = floorf(t);
    int   m  = (int)fm;
    float u  = t - fm;
    float u2 = u * u, u3 = u2 * u;
    float omu = 1.0f - u;
    const float S = 1.0f / 6.0f;
    float wA = omu * omu * omu * S;
    float wB = (3.0f * u3 - 6.0f * u2 + 4.0f) * S;
    float wC = (-3.0f * u3 + 3.0f * u2 + 3.0f * u + 1.0f) * S;
    float wD = u3 * S;

    float v[PERF];
    v[0] = 0.5f * xv * (1.0f + erff(xv * 0.70710678118654752f));
#pragma unroll
    for (int j = 0; j < NB; j++) {
        int d = j - m + 3;
        float bv = 0.0f;
        bv = (d == 0) ? wA : bv;
        bv = (d == 1) ? wB : bv;
        bv = (d == 2) ? wC : bv;
        bv = (d == 3) ? wD : bv;
        v[1 + j] = bv;
    }
    store12(v, dsth, dstl);
}

// ---------------- weight pack core ------------------------------------------
__device__ __forceinline__ void pack_elem(const float* __restrict__ bw, const float* __restrict__ sw,
                                          __nv_bfloat16* wh, __nv_bfloat16* wl, int IN, int e)
{
    float v[PERF];
    v[0] = bw[e];
#pragma unroll
    for (int j = 0; j < NB; j++) v[1 + j] = sw[(size_t)e * NB + j];
    int n = e / IN, i = e - n * IN;
    size_t base = (size_t)n * (IN * PERF) + (size_t)i * PERF;
    store12(v, wh + base, wl + base);
}

// ---------------- fused: expand x -> E0 + pack all weights (one launch) -----
__global__ void fused_init_kernel(const float* __restrict__ x,
                                  const float* __restrict__ bw0, const float* __restrict__ sw0,
                                  const float* __restrict__ bw1, const float* __restrict__ sw1,
                                  const float* __restrict__ bw2, const float* __restrict__ sw2)
{
    if (blockIdx.x < 8192) {
        int idx = blockIdx.x * blockDim.x + threadIdx.x;   // < 8192*256
        float xv = x[idx];
        size_t base = (size_t)idx * PERF;                  // row stride 256*12 = 3072
        expand_value(xv, g_Eh0 + base, g_El0 + base);
    } else {
        int t = (blockIdx.x - 8192) * blockDim.x + threadIdx.x;
        if (t < 131072)      pack_elem(bw0, sw0, g_Wh0, g_Wl0, 256, t);
        else if (t < 393216) pack_elem(bw1, sw1, g_Wh1, g_Wl1, 512, t - 131072);
        else                 pack_elem(bw2, sw2, g_Wh2, g_Wl2, 512, t - 393216);
    }
}

// ---------------- HMMA GEMM: 3-term hi/lo, fused epilogue -------------------
// CTA 128x128, 8 warps of 32x64 (4x2), K-chunk 32 (64B rows, SW64 swizzle),
// 2-stage cp.async, 64KB smem, forced 2 CTAs/SM -> 16 warps/SM.
// mode 0: C plain; mode 1: C with BN; mode 2: expand into dstEh/dstEl (512-col h).
#define TILE_B   8192
#define BUF_B    (4 * TILE_B)
#define SMEM_TOT (2 * BUF_B)   // 64 KB

__global__ void __launch_bounds__(256, 2)
kan_gemm(float* __restrict__ C,
         const __nv_bfloat16* __restrict__ Eh, const __nv_bfloat16* __restrict__ El,
         const __nv_bfloat16* __restrict__ Wh, const __nv_bfloat16* __restrict__ Wl,
         int N, int Kd, int NC, int mode,
         __nv_bfloat16* __restrict__ dstEh, __nv_bfloat16* __restrict__ dstEl,
         const float* __restrict__ gamma, const float* __restrict__ beta,
         const float* __restrict__ mean,  const float* __restrict__ var)
{
    extern __shared__ __align__(128) char smem[];
    const uint32_t sbase = smem_u32(smem);

    const int tid  = threadIdx.x;
    const int wid  = tid >> 5;
    const int lane = tid & 31;
    const int bm = blockIdx.y * 128, bn = blockIdx.x * 128;

    const int m_base = (wid & 3) * 32, n_base = (wid >> 2) * 64;

    const __nv_bfloat16* srcs[4] = {Eh, El, Wh, Wl};

    // loader: 128 rows x 64B per array; 256 threads -> 2 iters x (row tid>>2, col tid&3)
    const int lr0 = tid >> 2;       // 0..63
    const int lc  = tid & 3;        // 16B column
    uint32_t so_base[2];
#pragma unroll
    for (int it = 0; it < 2; it++) {
        uint32_t so = (uint32_t)((lr0 + 64 * it) * 64 + lc * 16);
        so_base[it] = so ^ ((so >> 3) & 0x30);   // SW64 swizzle
    }

    auto load_chunk = [&](int c) {
        int k0 = c * 32;
        uint32_t bufo = (uint32_t)(c & 1) * BUF_B;
#pragma unroll
        for (int arr = 0; arr < 4; arr++) {
            const __nv_bfloat16* p = srcs[arr];
            int rbase = (arr < 2) ? bm : bn;
            uint32_t dst0 = sbase + bufo + (uint32_t)arr * TILE_B;
#pragma unroll
            for (int it = 0; it < 2; it++) {
                int r = lr0 + 64 * it;
                cp16(dst0 + so_base[it], p + (size_t)(rbase + r) * Kd + k0 + lc * 8);
            }
        }
        cp_commit();
    };

    float acc[2][8][4];
#pragma unroll
    for (int mt = 0; mt < 2; mt++)
#pragma unroll
        for (int nt = 0; nt < 8; nt++)
#pragma unroll
            for (int e = 0; e < 4; e++) acc[mt][nt][e] = 0.0f;

    int a_row[2], b_row[4];
#pragma unroll
    for (int mt = 0; mt < 2; mt++)
        a_row[mt] = m_base + mt * 16 + (lane & 7) + ((lane >> 3) & 1) * 8;
#pragma unroll
    for (int ng = 0; ng < 4; ng++)
        b_row[ng] = n_base + ng * 16 + (lane & 7) + (lane >> 4) * 8;
    const int a_kb = (lane >> 4) * 16;
    const int b_kb = ((lane >> 3) & 1) * 16;

    load_chunk(0);

    for (int c = 0; c < NC; c++) {
        if (c + 1 < NC) { load_chunk(c + 1); cp_wait<1>(); }
        else             cp_wait<0>();
        __syncthreads();

        uint32_t bufo = (uint32_t)(c & 1) * BUF_B;
        uint32_t sAh = sbase + bufo;
        uint32_t sAl = sAh + TILE_B;
        uint32_t sBh = sAh + 2 * TILE_B;
        uint32_t sBl = sAh + 3 * TILE_B;

#pragma unroll
        for (int k16 = 0; k16 < 2; k16++) {
            int kb = k16 * 32;
            uint32_t bh[8][2], bl[8][2];
#pragma unroll
            for (int ng = 0; ng < 4; ng++) {
                uint32_t off = (uint32_t)(b_row[ng] * 64 + kb + b_kb);
                off ^= (off >> 3) & 0x30;
                uint32_t t[4];
                ldsm4(t, sBh + off);
                bh[ng * 2][0] = t[0]; bh[ng * 2][1] = t[1];
                bh[ng * 2 + 1][0] = t[2]; bh[ng * 2 + 1][1] = t[3];
                ldsm4(t, sBl + off);
                bl[ng * 2][0] = t[0]; bl[ng * 2][1] = t[1];
                bl[ng * 2 + 1][0] = t[2]; bl[ng * 2 + 1][1] = t[3];
            }
#pragma unroll
            for (int mt = 0; mt < 2; mt++) {
                uint32_t off = (uint32_t)(a_row[mt] * 64 + kb + a_kb);
                off ^= (off >> 3) & 0x30;
                uint32_t ah[4], al[4];
                ldsm4(ah, sAh + off);
                ldsm4(al, sAl + off);
#pragma unroll
                for (int nt = 0; nt < 8; nt++) {
                    mma16816(acc[mt][nt], ah, bh[nt]);
                    mma16816(acc[mt][nt], ah, bl[nt]);
                    mma16816(acc[mt][nt], al, bh[nt]);
                }
            }
        }
        __syncthreads();
    }

    const int g  = lane >> 2;
    const int tq = lane & 3;
#pragma unroll
    for (int mt = 0; mt < 2; mt++) {
        int row0 = bm + m_base + mt * 16 + g;
#pragma unroll
        for (int nt = 0; nt < 8; nt++) {
            int col = bn + n_base + nt * 8 + tq * 2;
            float v0 = acc[mt][nt][0], v1 = acc[mt][nt][1];
            float v2 = acc[mt][nt][2], v3 = acc[mt][nt][3];
            if (mode == 2) {
                // fused expansion: h tile -> next-layer E (row stride 512*12 = 6144)
                size_t b0 = ((size_t)row0 * 512 + col) * PERF;
                size_t b1 = ((size_t)(row0 + 8) * 512 + col) * PERF;
                expand_value(v0, dstEh + b0,        dstEl + b0);
                expand_value(v1, dstEh + b0 + PERF, dstEl + b0 + PERF);
                expand_value(v2, dstEh + b1,        dstEl + b1);
                expand_value(v3, dstEh + b1 + PERF, dstEl + b1 + PERF);
            } else {
                if (mode == 1) {
                    float s0 = gamma[col]     * rsqrtf(var[col]     + BN_EPS);
                    float s1 = gamma[col + 1] * rsqrtf(var[col + 1] + BN_EPS);
                    float m0 = mean[col], m1 = mean[col + 1];
                    float be0 = beta[col], be1 = beta[col + 1];
                    v0 = s0 * (v0 - m0) + be0;  v1 = s1 * (v1 - m1) + be1;
                    v2 = s0 * (v2 - m0) + be0;  v3 = s1 * (v3 - m1) + be1;
                }
                *(float2*)&C[(size_t)row0 * N + col]       = make_float2(v0, v1);
                *(float2*)&C[(size_t)(row0 + 8) * N + col] = make_float2(v2, v3);
            }
        }
    }
}

// ---------------- launch -----------------------------------------------------
extern "C" void kernel_launch(void* const* d_in, const int* in_sizes, int n_in,
                              void* d_out, int out_size)
{
    (void)in_sizes; (void)n_in; (void)out_size;
    const float* x         = (const float*)d_in[0];
    const float* base_w0   = (const float*)d_in[2];
    const float* spline_w0 = (const float*)d_in[3];
    const float* base_w1   = (const float*)d_in[5];
    const float* spline_w1 = (const float*)d_in[6];
    const float* base_w2   = (const float*)d_in[8];
    const float* spline_w2 = (const float*)d_in[9];
    const float* bn_gamma  = (const float*)d_in[10];
    const float* bn_beta   = (const float*)d_in[11];
    const float* bn_mean   = (const float*)d_in[12];
    const float* bn_var    = (const float*)d_in[13];
    float* out = (float*)d_out;

    __nv_bfloat16 *eh0, *el0, *eh1, *el1, *wh0, *wl0, *wh1, *wl1, *wh2, *wl2;
    cudaGetSymbolAddress((void**)&eh0, g_Eh0);
    cudaGetSymbolAddress((void**)&el0, g_El0);
    cudaGetSymbolAddress((void**)&eh1, g_Eh1);
    cudaGetSymbolAddress((void**)&el1, g_El1);
    cudaGetSymbolAddress((void**)&wh0, g_Wh0);
    cudaGetSymbolAddress((void**)&wl0, g_Wl0);
    cudaGetSymbolAddress((void**)&wh1, g_Wh1);
    cudaGetSymbolAddress((void**)&wl1, g_Wl1);
    cudaGetSymbolAddress((void**)&wh2, g_Wh2);
    cudaGetSymbolAddress((void**)&wl2, g_Wl2);

    cudaFuncSetAttribute(kan_gemm, cudaFuncAttributeMaxDynamicSharedMemorySize, SMEM_TOT);

    const int TB = 256;

    // 1: expand x -> E0 (stride 3072) + pack all weights
    fused_init_kernel<<<8192 + 2048, TB>>>(x, base_w0, spline_w0,
                                           base_w1, spline_w1, base_w2, spline_w2);
    // 2: layer0 GEMM (E0,K=3072) -> fused expansion -> E1 (stride 6144)
    {
        dim3 g(512 / 128, BATCH / 128);
        kan_gemm<<<g, 256, SMEM_TOT>>>(out, eh0, el0, wh0, wl0, 512, 3072, 96, 2,
                                       eh1, el1, nullptr, nullptr, nullptr, nullptr);
    }
    // 3: layer1 GEMM (E1,K=6144) -> fused expansion -> E0 (stride 6144)
    {
        dim3 g(512 / 128, BATCH / 128);
        kan_gemm<<<g, 256, SMEM_TOT>>>(out, eh1, el1, wh1, wl1, 512, 6144, 192, 2,
                                       eh0, el0, nullptr, nullptr, nullptr, nullptr);
    }
    // 4: layer2 GEMM (E0,K=6144) -> BN -> out   (ncu overall slot #6)
    {
        dim3 g(256 / 128, BATCH / 128);
        kan_gemm<<<g, 256, SMEM_TOT>>>(out, eh0, el0, wh2, wl2, 256, 6144, 192, 1,
                                       nullptr, nullptr, bn_gamma, bn_beta, bn_mean, bn_var);
    }
}

// round 14
// speedup vs baseline: 1.0509x; 1.0509x over previous
#include <cuda_runtime.h>
#include <cuda_bf16.h>
#include <math.h>
#include <stdint.h>

#define BATCH 8192
#define NB    11
#define PERF  12
#define BN_EPS 1e-5f

// ---------------- static scratch (no runtime allocation) --------------------
// ping-pong expanded activations (8192 x 6144 bf16 each)
static __device__ __align__(128) __nv_bfloat16 g_Eh0[BATCH * 6144];
static __device__ __align__(128) __nv_bfloat16 g_El0[BATCH * 6144];
static __device__ __align__(128) __nv_bfloat16 g_Eh1[BATCH * 6144];
static __device__ __align__(128) __nv_bfloat16 g_El1[BATCH * 6144];
static __device__ __align__(128) __nv_bfloat16 g_Wh0[3072 * 512];
static __device__ __align__(128) __nv_bfloat16 g_Wl0[3072 * 512];
static __device__ __align__(128) __nv_bfloat16 g_Wh1[6144 * 512];
static __device__ __align__(128) __nv_bfloat16 g_Wl1[6144 * 512];
static __device__ __align__(128) __nv_bfloat16 g_Wh2[6144 * 256];
static __device__ __align__(128) __nv_bfloat16 g_Wl2[6144 * 256];

// ---------------- PTX helpers (family-target safe: sm_80+ ISA only) ---------
__device__ __forceinline__ uint32_t smem_u32(const void* p) {
    uint32_t a;
    asm("{ .reg .u64 t; cvta.to.shared.u64 t, %1; cvt.u32.u64 %0, t; }" : "=r"(a) : "l"(p));
    return a;
}
__device__ __forceinline__ void ldsm4(uint32_t* r, uint32_t addr) {
    asm volatile("ldmatrix.sync.aligned.m8n8.x4.shared.b16 {%0,%1,%2,%3}, [%4];"
                 : "=r"(r[0]), "=r"(r[1]), "=r"(r[2]), "=r"(r[3]) : "r"(addr));
}
__device__ __forceinline__ void mma16816(float* d, const uint32_t* a, const uint32_t* b) {
    asm volatile("mma.sync.aligned.m16n8k16.row.col.f32.bf16.bf16.f32 "
                 "{%0,%1,%2,%3}, {%4,%5,%6,%7}, {%8,%9}, {%0,%1,%2,%3};"
                 : "+f"(d[0]), "+f"(d[1]), "+f"(d[2]), "+f"(d[3])
                 : "r"(a[0]), "r"(a[1]), "r"(a[2]), "r"(a[3]), "r"(b[0]), "r"(b[1]));
}
__device__ __forceinline__ void cp16(uint32_t dst, const void* src) {
    asm volatile("cp.async.cg.shared.global [%0], [%1], 16;" :: "r"(dst), "l"(src));
}
__device__ __forceinline__ void cp_commit() { asm volatile("cp.async.commit_group;" ::: "memory"); }
template <int W> __device__ __forceinline__ void cp_wait() {
    asm volatile("cp.async.wait_group %0;" :: "n"(W) : "memory");
}

// packed hi/lo quantization: 2 values -> 1 bf16x2 hi word + 1 bf16x2 lo word
__device__ __forceinline__ void quant_pair(float v0, float v1, uint32_t& ph, uint32_t& pl) {
    uint32_t h;
    asm("cvt.rn.bf16x2.f32 %0, %1, %2;" : "=r"(h) : "f"(v1), "f"(v0));
    float h0 = __uint_as_float(h << 16);
    float h1 = __uint_as_float(h & 0xFFFF0000u);
    uint32_t l;
    float l0 = v0 - h0, l1 = v1 - h1;
    asm("cvt.rn.bf16x2.f32 %0, %1, %2;" : "=r"(l) : "f"(l1), "f"(l0));
    ph = h; pl = l;
}

__device__ __forceinline__ void store12(const float* v, __nv_bfloat16* dsth, __nv_bfloat16* dstl) {
    uint32_t ph[6], pl[6];
#pragma unroll
    for (int p = 0; p < 6; p++) quant_pair(v[2 * p], v[2 * p + 1], ph[p], pl[p]);
    uint2* dh = (uint2*)dsth;
    uint2* dl = (uint2*)dstl;
    dh[0] = make_uint2(ph[0], ph[1]); dh[1] = make_uint2(ph[2], ph[3]); dh[2] = make_uint2(ph[4], ph[5]);
    dl[0] = make_uint2(pl[0], pl[1]); dl[1] = make_uint2(pl[2], pl[3]); dl[2] = make_uint2(pl[4], pl[5]);
}

// ---------------- expansion core (closed-form uniform cubic B-splines) ------
__device__ __forceinline__ void expand_value(float xv, __nv_bfloat16* dsth, __nv_bfloat16* dstl) {
    float t  = (xv + 1.75f) * 4.0f;
    float fm = floorf(t);
    int   m  = (int)fm;
    float u  = t - fm;
    float u2 = u * u, u3 = u2 * u;
    float omu = 1.0f - u;
    const float S = 1.0f / 6.0f;
    float wA = omu * omu * omu * S;
    float wB = (3.0f * u3 - 6.0f * u2 + 4.0f) * S;
    float wC = (-3.0f * u3 + 3.0f * u2 + 3.0f * u + 1.0f) * S;
    float wD = u3 * S;

    float v[PERF];
    v[0] = 0.5f * xv * (1.0f + erff(xv * 0.70710678118654752f));
#pragma unroll
    for (int j = 0; j < NB; j++) {
        int d = j - m + 3;
        float bv = 0.0f;
        bv = (d == 0) ? wA : bv;
        bv = (d == 1) ? wB : bv;
        bv = (d == 2) ? wC : bv;
        bv = (d == 3) ? wD : bv;
        v[1 + j] = bv;
    }
    store12(v, dsth, dstl);
}

// ---------------- weight pack core ------------------------------------------
__device__ __forceinline__ void pack_elem(const float* __restrict__ bw, const float* __restrict__ sw,
                                          __nv_bfloat16* wh, __nv_bfloat16* wl, int IN, int e)
{
    float v[PERF];
    v[0] = bw[e];
#pragma unroll
    for (int j = 0; j < NB; j++) v[1 + j] = sw[(size_t)e * NB + j];
    int n = e / IN, i = e - n * IN;
    size_t base = (size_t)n * (IN * PERF) + (size_t)i * PERF;
    store12(v, wh + base, wl + base);
}

// ---------------- fused: expand x -> E0 + pack all weights (one launch) -----
__global__ void fused_init_kernel(const float* __restrict__ x,
                                  const float* __restrict__ bw0, const float* __restrict__ sw0,
                                  const float* __restrict__ bw1, const float* __restrict__ sw1,
                                  const float* __restrict__ bw2, const float* __restrict__ sw2)
{
    if (blockIdx.x < 8192) {
        int idx = blockIdx.x * blockDim.x + threadIdx.x;   // < 8192*256
        float xv = x[idx];
        size_t base = (size_t)idx * PERF;                  // row stride 256*12 = 3072
        expand_value(xv, g_Eh0 + base, g_El0 + base);
    } else {
        int t = (blockIdx.x - 8192) * blockDim.x + threadIdx.x;
        if (t < 131072)      pack_elem(bw0, sw0, g_Wh0, g_Wl0, 256, t);
        else if (t < 393216) pack_elem(bw1, sw1, g_Wh1, g_Wl1, 512, t - 131072);
        else                 pack_elem(bw2, sw2, g_Wh2, g_Wl2, 512, t - 393216);
    }
}

// ---------------- HMMA GEMM: 3-term hi/lo, fused epilogue -------------------
// R11 proven shape: CTA 128x128, 4 warps of 64x64, K-chunk 32 (64B rows, SW64),
// 3-stage cp.async, 96KB smem -> 2 CTAs/SM, 255 regs (no spill).
// mode 0: C plain; mode 1: C with BN; mode 2: expand into dstEh/dstEl (512-col h).
#define TILE_B   8192
#define BUF_B    (4 * TILE_B)
#define SMEM_TOT (3 * BUF_B)   // 96 KB

__global__ void __launch_bounds__(128, 2)
kan_gemm(float* __restrict__ C,
         const __nv_bfloat16* __restrict__ Eh, const __nv_bfloat16* __restrict__ El,
         const __nv_bfloat16* __restrict__ Wh, const __nv_bfloat16* __restrict__ Wl,
         int N, int Kd, int NC, int mode,
         __nv_bfloat16* __restrict__ dstEh, __nv_bfloat16* __restrict__ dstEl,
         const float* __restrict__ gamma, const float* __restrict__ beta,
         const float* __restrict__ mean,  const float* __restrict__ var)
{
    extern __shared__ __align__(128) char smem[];
    const uint32_t sbase = smem_u32(smem);

    const int tid  = threadIdx.x;
    const int wid  = tid >> 5;
    const int lane = tid & 31;
    const int bm = blockIdx.y * 128, bn = blockIdx.x * 128;

    const int m_base = (wid & 1) * 64, n_base = (wid >> 1) * 64;

    const __nv_bfloat16* srcs[4] = {Eh, El, Wh, Wl};

    // loader: 64B rows; 128 threads -> 4 row-iters x 4 col-chunks
    const int lr0 = tid >> 2;       // 0..31
    const int lc  = tid & 3;        // 16B column within 64B row
    uint32_t so_base[4];
#pragma unroll
    for (int it = 0; it < 4; it++) {
        uint32_t so = (uint32_t)((lr0 + 32 * it) * 64 + lc * 16);
        so_base[it] = so ^ ((so >> 3) & 0x30);   // SW64 swizzle
    }

    auto load_chunk = [&](int c) {
        int k0 = c * 32;
        uint32_t bufo = (uint32_t)(c % 3) * BUF_B;
#pragma unroll
        for (int arr = 0; arr < 4; arr++) {
            const __nv_bfloat16* p = srcs[arr];
            int rbase = (arr < 2) ? bm : bn;
            uint32_t dst0 = sbase + bufo + (uint32_t)arr * TILE_B;
#pragma unroll
            for (int it = 0; it < 4; it++) {
                int r = lr0 + 32 * it;
                cp16(dst0 + so_base[it], p + (size_t)(rbase + r) * Kd + k0 + lc * 8);
            }
        }
        cp_commit();
    };

    float acc[4][8][4];
#pragma unroll
    for (int mt = 0; mt < 4; mt++)
#pragma unroll
        for (int nt = 0; nt < 8; nt++)
#pragma unroll
            for (int e = 0; e < 4; e++) acc[mt][nt][e] = 0.0f;

    int a_row[4], b_row[4];
#pragma unroll
    for (int mt = 0; mt < 4; mt++)
        a_row[mt] = m_base + mt * 16 + (lane & 7) + ((lane >> 3) & 1) * 8;
#pragma unroll
    for (int ng = 0; ng < 4; ng++)
        b_row[ng] = n_base + ng * 16 + (lane & 7) + (lane >> 4) * 8;
    const int a_kb = (lane >> 4) * 16;
    const int b_kb = ((lane >> 3) & 1) * 16;

    load_chunk(0);
    if (NC > 1) load_chunk(1);

    for (int c = 0; c < NC; c++) {
        if (c + 2 < NC) { load_chunk(c + 2); cp_wait<2>(); }
        else if (c + 1 < NC) cp_wait<1>();
        else                 cp_wait<0>();
        __syncthreads();

        uint32_t bufo = (uint32_t)(c % 3) * BUF_B;
        uint32_t sAh = sbase + bufo;
        uint32_t sAl = sAh + TILE_B;
        uint32_t sBh = sAh + 2 * TILE_B;
        uint32_t sBl = sAh + 3 * TILE_B;

#pragma unroll
        for (int k16 = 0; k16 < 2; k16++) {
            int kb = k16 * 32;
            uint32_t bh[8][2], bl[8][2];
#pragma unroll
            for (int ng = 0; ng < 4; ng++) {
                uint32_t off = (uint32_t)(b_row[ng] * 64 + kb + b_kb);
                off ^= (off >> 3) & 0x30;
                uint32_t t[4];
                ldsm4(t, sBh + off);
                bh[ng * 2][0] = t[0]; bh[ng * 2][1] = t[1];
                bh[ng * 2 + 1][0] = t[2]; bh[ng * 2 + 1][1] = t[3];
                ldsm4(t, sBl + off);
                bl[ng * 2][0] = t[0]; bl[ng * 2][1] = t[1];
                bl[ng * 2 + 1][0] = t[2]; bl[ng * 2 + 1][1] = t[3];
            }
#pragma unroll
            for (int mt = 0; mt < 4; mt++) {
                uint32_t off = (uint32_t)(a_row[mt] * 64 + kb + a_kb);
                off ^= (off >> 3) & 0x30;
                uint32_t ah[4], al[4];
                ldsm4(ah, sAh + off);
                ldsm4(al, sAl + off);
#pragma unroll
                for (int nt = 0; nt < 8; nt++) {
                    mma16816(acc[mt][nt], ah, bh[nt]);
                    mma16816(acc[mt][nt], ah, bl[nt]);
                    mma16816(acc[mt][nt], al, bh[nt]);
                }
            }
        }
        __syncthreads();
    }

    const int g  = lane >> 2;
    const int tq = lane & 3;
#pragma unroll
    for (int mt = 0; mt < 4; mt++) {
        int row0 = bm + m_base + mt * 16 + g;
#pragma unroll
        for (int nt = 0; nt < 8; nt++) {
            int col = bn + n_base + nt * 8 + tq * 2;
            float v0 = acc[mt][nt][0], v1 = acc[mt][nt][1];
            float v2 = acc[mt][nt][2], v3 = acc[mt][nt][3];
            if (mode == 2) {
                // fused expansion: h tile -> next-layer E (row stride 512*12 = 6144)
                size_t b0 = ((size_t)row0 * 512 + col) * PERF;
                size_t b1 = ((size_t)(row0 + 8) * 512 + col) * PERF;
                expand_value(v0, dstEh + b0,        dstEl + b0);
                expand_value(v1, dstEh + b0 + PERF, dstEl + b0 + PERF);
                expand_value(v2, dstEh + b1,        dstEl + b1);
                expand_value(v3, dstEh + b1 + PERF, dstEl + b1 + PERF);
            } else {
                if (mode == 1) {
                    float s0 = gamma[col]     * rsqrtf(var[col]     + BN_EPS);
                    float s1 = gamma[col + 1] * rsqrtf(var[col + 1] + BN_EPS);
                    float m0 = mean[col], m1 = mean[col + 1];
                    float be0 = beta[col], be1 = beta[col + 1];
                    v0 = s0 * (v0 - m0) + be0;  v1 = s1 * (v1 - m1) + be1;
                    v2 = s0 * (v2 - m0) + be0;  v3 = s1 * (v3 - m1) + be1;
                }
                *(float2*)&C[(size_t)row0 * N + col]       = make_float2(v0, v1);
                *(float2*)&C[(size_t)(row0 + 8) * N + col] = make_float2(v2, v3);
            }
        }
    }
}

// ---------------- launch -----------------------------------------------------
extern "C" void kernel_launch(void* const* d_in, const int* in_sizes, int n_in,
                              void* d_out, int out_size)
{
    (void)in_sizes; (void)n_in; (void)out_size;
    const float* x         = (const float*)d_in[0];
    const float* base_w0   = (const float*)d_in[2];
    const float* spline_w0 = (const float*)d_in[3];
    const float* base_w1   = (const float*)d_in[5];
    const float* spline_w1 = (const float*)d_in[6];
    const float* base_w2   = (const float*)d_in[8];
    const float* spline_w2 = (const float*)d_in[9];
    const float* bn_gamma  = (const float*)d_in[10];
    const float* bn_beta   = (const float*)d_in[11];
    const float* bn_mean   = (const float*)d_in[12];
    const float* bn_var    = (const float*)d_in[13];
    float* out = (float*)d_out;

    __nv_bfloat16 *eh0, *el0, *eh1, *el1, *wh0, *wl0, *wh1, *wl1, *wh2, *wl2;
    cudaGetSymbolAddress((void**)&eh0, g_Eh0);
    cudaGetSymbolAddress((void**)&el0, g_El0);
    cudaGetSymbolAddress((void**)&eh1, g_Eh1);
    cudaGetSymbolAddress((void**)&el1, g_El1);
    cudaGetSymbolAddress((void**)&wh0, g_Wh0);
    cudaGetSymbolAddress((void**)&wl0, g_Wl0);
    cudaGetSymbolAddress((void**)&wh1, g_Wh1);
    cudaGetSymbolAddress((void**)&wl1, g_Wl1);
    cudaGetSymbolAddress((void**)&wh2, g_Wh2);
    cudaGetSymbolAddress((void**)&wl2, g_Wl2);

    cudaFuncSetAttribute(kan_gemm, cudaFuncAttributeMaxDynamicSharedMemorySize, SMEM_TOT);

    const int TB = 256;

    // 1: expand x -> E0 (stride 3072) + pack all weights
    fused_init_kernel<<<8192 + 2048, TB>>>(x, base_w0, spline_w0,
                                           base_w1, spline_w1, base_w2, spline_w2);
    // 2: layer0 GEMM (E0,K=3072) -> fused expansion -> E1 (stride 6144)
    {
        dim3 g(512 / 128, BATCH / 128);
        kan_gemm<<<g, 128, SMEM_TOT>>>(out, eh0, el0, wh0, wl0, 512, 3072, 96, 2,
                                       eh1, el1, nullptr, nullptr, nullptr, nullptr);
    }
    // 3: layer1 GEMM (E1,K=6144) -> fused expansion -> E0 (stride 6144)
    {
        dim3 g(512 / 128, BATCH / 128);
        kan_gemm<<<g, 128, SMEM_TOT>>>(out, eh1, el1, wh1, wl1, 512, 6144, 192, 2,
                                       eh0, el0, nullptr, nullptr, nullptr, nullptr);
    }
    // 4: layer2 GEMM (E0,K=6144) -> BN -> out   (ncu overall slot #6)
    {
        dim3 g(256 / 128, BATCH / 128);
        kan_gemm<<<g, 128, SMEM_TOT>>>(out, eh0, el0, wh2, wl2, 256, 6144, 192, 1,
                                       nullptr, nullptr, bn_gamma, bn_beta, bn_mean, bn_var);
    }
}

// round 15
// speedup vs baseline: 1.2301x; 1.1705x over previous
#include <cuda_runtime.h>
#include <cuda_bf16.h>
#include <math.h>
#include <stdint.h>

#define BATCH 8192
#define NB    11
#define PERF  12
#define BN_EPS 1e-5f

// ---------------- static scratch (no runtime allocation) --------------------
static __device__ __align__(128) __nv_bfloat16 g_Eh[BATCH * 6144];
static __device__ __align__(128) __nv_bfloat16 g_El[BATCH * 6144];
static __device__ __align__(128) __nv_bfloat16 g_Wh0[3072 * 512];
static __device__ __align__(128) __nv_bfloat16 g_Wl0[3072 * 512];
static __device__ __align__(128) __nv_bfloat16 g_Wh1[6144 * 512];
static __device__ __align__(128) __nv_bfloat16 g_Wl1[6144 * 512];
static __device__ __align__(128) __nv_bfloat16 g_Wh2[6144 * 256];
static __device__ __align__(128) __nv_bfloat16 g_Wl2[6144 * 256];
static __device__ float g_h[BATCH * 512];

// ---------------- PTX helpers (family-target safe: sm_80+ ISA only) ---------
__device__ __forceinline__ uint32_t smem_u32(const void* p) {
    uint32_t a;
    asm("{ .reg .u64 t; cvta.to.shared.u64 t, %1; cvt.u32.u64 %0, t; }" : "=r"(a) : "l"(p));
    return a;
}
__device__ __forceinline__ void ldsm4(uint32_t* r, uint32_t addr) {
    asm volatile("ldmatrix.sync.aligned.m8n8.x4.shared.b16 {%0,%1,%2,%3}, [%4];"
                 : "=r"(r[0]), "=r"(r[1]), "=r"(r[2]), "=r"(r[3]) : "r"(addr));
}
__device__ __forceinline__ void mma16816(float* d, const uint32_t* a, const uint32_t* b) {
    asm volatile("mma.sync.aligned.m16n8k16.row.col.f32.bf16.bf16.f32 "
                 "{%0,%1,%2,%3}, {%4,%5,%6,%7}, {%8,%9}, {%0,%1,%2,%3};"
                 : "+f"(d[0]), "+f"(d[1]), "+f"(d[2]), "+f"(d[3])
                 : "r"(a[0]), "r"(a[1]), "r"(a[2]), "r"(a[3]), "r"(b[0]), "r"(b[1]));
}
__device__ __forceinline__ void cp16(uint32_t dst, const void* src) {
    asm volatile("cp.async.cg.shared.global [%0], [%1], 16;" :: "r"(dst), "l"(src));
}
__device__ __forceinline__ void cp_commit() { asm volatile("cp.async.commit_group;" ::: "memory"); }
template <int W> __device__ __forceinline__ void cp_wait() {
    asm volatile("cp.async.wait_group %0;" :: "n"(W) : "memory");
}

// packed hi/lo quantization
__device__ __forceinline__ void quant_pair(float v0, float v1, uint32_t& ph, uint32_t& pl) {
    uint32_t h;
    asm("cvt.rn.bf16x2.f32 %0, %1, %2;" : "=r"(h) : "f"(v1), "f"(v0));
    float h0 = __uint_as_float(h << 16);
    float h1 = __uint_as_float(h & 0xFFFF0000u);
    uint32_t l;
    float l0 = v0 - h0, l1 = v1 - h1;
    asm("cvt.rn.bf16x2.f32 %0, %1, %2;" : "=r"(l) : "f"(l1), "f"(l0));
    ph = h; pl = l;
}

__device__ __forceinline__ void store12(const float* v, __nv_bfloat16* dsth, __nv_bfloat16* dstl) {
    uint32_t ph[6], pl[6];
#pragma unroll
    for (int p = 0; p < 6; p++) quant_pair(v[2 * p], v[2 * p + 1], ph[p], pl[p]);
    uint2* dh = (uint2*)dsth;
    uint2* dl = (uint2*)dstl;
    dh[0] = make_uint2(ph[0], ph[1]); dh[1] = make_uint2(ph[2], ph[3]); dh[2] = make_uint2(ph[4], ph[5]);
    dl[0] = make_uint2(pl[0], pl[1]); dl[1] = make_uint2(pl[2], pl[3]); dl[2] = make_uint2(pl[4], pl[5]);
}

// ---------------- expansion core (closed-form uniform cubic B-splines) ------
__device__ __forceinline__ void expand_elem(const float* __restrict__ xin, int IN, int idx) {
    int b = idx / IN;
    int i = idx - b * IN;
    float xv = xin[(size_t)b * IN + i];

    float t  = (xv + 1.75f) * 4.0f;
    float fm = floorf(t);
    int   m  = (int)fm;
    float u  = t - fm;
    float u2 = u * u, u3 = u2 * u;
    float omu = 1.0f - u;
    const float S = 1.0f / 6.0f;
    float wA = omu * omu * omu * S;
    float wB = (3.0f * u3 - 6.0f * u2 + 4.0f) * S;
    float wC = (-3.0f * u3 + 3.0f * u2 + 3.0f * u + 1.0f) * S;
    float wD = u3 * S;

    float v[PERF];
    v[0] = 0.5f * xv * (1.0f + erff(xv * 0.70710678118654752f));
#pragma unroll
    for (int j = 0; j < NB; j++) {
        int d = j - m + 3;
        float bv = 0.0f;
        bv = (d == 0) ? wA : bv;
        bv = (d == 1) ? wB : bv;
        bv = (d == 2) ? wC : bv;
        bv = (d == 3) ? wD : bv;
        v[1 + j] = bv;
    }
    size_t base = ((size_t)b * IN + i) * PERF;
    store12(v, g_Eh + base, g_El + base);
}

__global__ void expand_kernel(const float* __restrict__ xin, int IN) {
    int idx = blockIdx.x * blockDim.x + threadIdx.x;
    if (idx < BATCH * IN) expand_elem(xin, IN, idx);
}

// ---------------- weight pack core ------------------------------------------
__device__ __forceinline__ void pack_elem(const float* __restrict__ bw, const float* __restrict__ sw,
                                          __nv_bfloat16* wh, __nv_bfloat16* wl, int IN, int e)
{
    float v[PERF];
    v[0] = bw[e];
#pragma unroll
    for (int j = 0; j < NB; j++) v[1 + j] = sw[(size_t)e * NB + j];
    int n = e / IN, i = e - n * IN;
    size_t base = (size_t)n * (IN * PERF) + (size_t)i * PERF;
    store12(v, wh + base, wl + base);
}

// ---------------- fused: expand layer-0 + pack all weights ------------------
__global__ void fused_init_kernel(const float* __restrict__ x,
                                  const float* __restrict__ bw0, const float* __restrict__ sw0,
                                  const float* __restrict__ bw1, const float* __restrict__ sw1,
                                  const float* __restrict__ bw2, const float* __restrict__ sw2)
{
    if (blockIdx.x < 8192) {
        int idx = blockIdx.x * blockDim.x + threadIdx.x;
        expand_elem(x, 256, idx);
    } else {
        int t = (blockIdx.x - 8192) * blockDim.x + threadIdx.x;
        if (t < 131072)      pack_elem(bw0, sw0, g_Wh0, g_Wl0, 256, t);
        else if (t < 393216) pack_elem(bw1, sw1, g_Wh1, g_Wl1, 512, t - 131072);
        else                 pack_elem(bw2, sw2, g_Wh2, g_Wl2, 512, t - 393216);
    }
}

// ---------------- HMMA GEMM (templated M-tile): 3-term hi/lo ----------------
// MT=128: CTA 128x128, 4 warps of 64x64 (R11 proven shape).
// MT=64 : CTA  64x128, 4 warps of 32x64 (for grid-starved layers).
// K-chunk 32 (64B rows, SW64 swizzle), 3-stage cp.async, 2 CTAs/SM.
#define TB_B 8192                      // B tile bytes: 128 x 64B

template <int MT>
__global__ void __launch_bounds__(128, 2)
kan_gemm(float* __restrict__ C,
         const __nv_bfloat16* __restrict__ Eh, const __nv_bfloat16* __restrict__ El,
         const __nv_bfloat16* __restrict__ Wh, const __nv_bfloat16* __restrict__ Wl,
         int N, int Kd, int NC, int do_bn,
         const float* __restrict__ gamma, const float* __restrict__ beta,
         const float* __restrict__ mean,  const float* __restrict__ var)
{
    constexpr int TA_B  = MT * 64;            // A tile bytes
    constexpr int BUF_B = 2 * TA_B + 2 * TB_B;
    constexpr int WM    = MT / 2;             // per-warp M extent
    constexpr int MI    = WM / 16;            // m16 tiles per warp

    extern __shared__ __align__(128) char smem[];
    const uint32_t sbase = smem_u32(smem);

    const int tid  = threadIdx.x;
    const int wid  = tid >> 5;
    const int lane = tid & 31;
    const int bm = blockIdx.y * MT, bn = blockIdx.x * 128;

    const int m_base = (wid & 1) * WM, n_base = (wid >> 1) * 64;

    const __nv_bfloat16* srcs[4] = {Eh, El, Wh, Wl};

    const int lr0 = tid >> 2;       // 0..31
    const int lc  = tid & 3;        // 16B column within 64B row
    uint32_t so_base[4];
#pragma unroll
    for (int it = 0; it < 4; it++) {
        uint32_t so = (uint32_t)((lr0 + 32 * it) * 64 + lc * 16);
        so_base[it] = so ^ ((so >> 3) & 0x30);   // SW64 swizzle
    }

    auto load_chunk = [&](int c) {
        int k0 = c * 32;
        uint32_t bufo = (uint32_t)(c % 3) * BUF_B;
#pragma unroll
        for (int arr = 0; arr < 4; arr++) {
            const __nv_bfloat16* p = srcs[arr];
            int rbase = (arr < 2) ? bm : bn;
            int nrows = (arr < 2) ? MT : 128;
            uint32_t dst0 = sbase + bufo
                          + ((arr < 2) ? (uint32_t)arr * TA_B
                                       : (uint32_t)(2 * TA_B + (arr - 2) * TB_B));
#pragma unroll
            for (int it = 0; it < 4; it++) {
                int r = lr0 + 32 * it;
                if (r < nrows)
                    cp16(dst0 + so_base[it], p + (size_t)(rbase + r) * Kd + k0 + lc * 8);
            }
        }
        cp_commit();
    };

    float acc[MI][8][4];
#pragma unroll
    for (int mt = 0; mt < MI; mt++)
#pragma unroll
        for (int nt = 0; nt < 8; nt++)
#pragma unroll
            for (int e = 0; e < 4; e++) acc[mt][nt][e] = 0.0f;

    int a_row[MI], b_row[4];
#pragma unroll
    for (int mt = 0; mt < MI; mt++)
        a_row[mt] = m_base + mt * 16 + (lane & 7) + ((lane >> 3) & 1) * 8;
#pragma unroll
    for (int ng = 0; ng < 4; ng++)
        b_row[ng] = n_base + ng * 16 + (lane & 7) + (lane >> 4) * 8;
    const int a_kb = (lane >> 4) * 16;
    const int b_kb = ((lane >> 3) & 1) * 16;

    load_chunk(0);
    if (NC > 1) load_chunk(1);

    for (int c = 0; c < NC; c++) {
        if (c + 2 < NC) { load_chunk(c + 2); cp_wait<2>(); }
        else if (c + 1 < NC) cp_wait<1>();
        else                 cp_wait<0>();
        __syncthreads();

        uint32_t bufo = (uint32_t)(c % 3) * BUF_B;
        uint32_t sAh = sbase + bufo;
        uint32_t sAl = sAh + TA_B;
        uint32_t sBh = sAh + 2 * TA_B;
        uint32_t sBl = sBh + TB_B;

#pragma unroll
        for (int k16 = 0; k16 < 2; k16++) {
            int kb = k16 * 32;
            uint32_t bh[8][2], bl[8][2];
#pragma unroll
            for (int ng = 0; ng < 4; ng++) {
                uint32_t off = (uint32_t)(b_row[ng] * 64 + kb + b_kb);
                off ^= (off >> 3) & 0x30;
                uint32_t t[4];
                ldsm4(t, sBh + off);
                bh[ng * 2][0] = t[0]; bh[ng * 2][1] = t[1];
                bh[ng * 2 + 1][0] = t[2]; bh[ng * 2 + 1][1] = t[3];
                ldsm4(t, sBl + off);
                bl[ng * 2][0] = t[0]; bl[ng * 2][1] = t[1];
                bl[ng * 2 + 1][0] = t[2]; bl[ng * 2 + 1][1] = t[3];
            }
#pragma unroll
            for (int mt = 0; mt < MI; mt++) {
                uint32_t off = (uint32_t)(a_row[mt] * 64 + kb + a_kb);
                off ^= (off >> 3) & 0x30;
                uint32_t ah[4], al[4];
                ldsm4(ah, sAh + off);
                ldsm4(al, sAl + off);
#pragma unroll
                for (int nt = 0; nt < 8; nt++) {
                    mma16816(acc[mt][nt], ah, bh[nt]);
                    mma16816(acc[mt][nt], ah, bl[nt]);
                    mma16816(acc[mt][nt], al, bh[nt]);
                }
            }
        }
        __syncthreads();
    }

    const int g  = lane >> 2;
    const int tq = lane & 3;
#pragma unroll
    for (int mt = 0; mt < MI; mt++) {
        int row0 = bm + m_base + mt * 16 + g;
#pragma unroll
        for (int nt = 0; nt < 8; nt++) {
            int col = bn + n_base + nt * 8 + tq * 2;
            float v0 = acc[mt][nt][0], v1 = acc[mt][nt][1];
            float v2 = acc[mt][nt][2], v3 = acc[mt][nt][3];
            if (do_bn) {
                float s0 = gamma[col]     * rsqrtf(var[col]     + BN_EPS);
                float s1 = gamma[col + 1] * rsqrtf(var[col + 1] + BN_EPS);
                float m0 = mean[col], m1 = mean[col + 1];
                float b0 = beta[col], b1 = beta[col + 1];
                v0 = s0 * (v0 - m0) + b0;  v1 = s1 * (v1 - m1) + b1;
                v2 = s0 * (v2 - m0) + b0;  v3 = s1 * (v3 - m1) + b1;
            }
            *(float2*)&C[(size_t)row0 * N + col]       = make_float2(v0, v1);
            *(float2*)&C[(size_t)(row0 + 8) * N + col] = make_float2(v2, v3);
        }
    }
}

// ---------------- launch -----------------------------------------------------
extern "C" void kernel_launch(void* const* d_in, const int* in_sizes, int n_in,
                              void* d_out, int out_size)
{
    (void)in_sizes; (void)n_in; (void)out_size;
    const float* x         = (const float*)d_in[0];
    const float* base_w0   = (const float*)d_in[2];
    const float* spline_w0 = (const float*)d_in[3];
    const float* base_w1   = (const float*)d_in[5];
    const float* spline_w1 = (const float*)d_in[6];
    const float* base_w2   = (const float*)d_in[8];
    const float* spline_w2 = (const float*)d_in[9];
    const float* bn_gamma  = (const float*)d_in[10];
    const float* bn_beta   = (const float*)d_in[11];
    const float* bn_mean   = (const float*)d_in[12];
    const float* bn_var    = (const float*)d_in[13];
    float* out = (float*)d_out;

    float* hptr = nullptr;
    cudaGetSymbolAddress((void**)&hptr, g_h);
    __nv_bfloat16 *eh, *el, *wh0, *wl0, *wh1, *wl1, *wh2, *wl2;
    cudaGetSymbolAddress((void**)&eh,  g_Eh);
    cudaGetSymbolAddress((void**)&el,  g_El);
    cudaGetSymbolAddress((void**)&wh0, g_Wh0);
    cudaGetSymbolAddress((void**)&wl0, g_Wl0);
    cudaGetSymbolAddress((void**)&wh1, g_Wh1);
    cudaGetSymbolAddress((void**)&wl1, g_Wl1);
    cudaGetSymbolAddress((void**)&wh2, g_Wh2);
    cudaGetSymbolAddress((void**)&wl2, g_Wl2);

    const int SMEM128 = 3 * (2 * 128 * 64 + 2 * TB_B);   // 96 KB
    const int SMEM64  = 3 * (2 * 64 * 64 + 2 * TB_B);    // 72 KB
    cudaFuncSetAttribute(kan_gemm<128>, cudaFuncAttributeMaxDynamicSharedMemorySize, SMEM128);
    cudaFuncSetAttribute(kan_gemm<64>,  cudaFuncAttributeMaxDynamicSharedMemorySize, SMEM64);

    const int TB = 256;

    // 1: expand x -> E + pack all weights
    fused_init_kernel<<<8192 + 2048, TB>>>(x, base_w0, spline_w0,
                                           base_w1, spline_w1, base_w2, spline_w2);
    // 2: layer0 GEMM (K=3072) -> h
    {
        dim3 g(512 / 128, BATCH / 128);
        kan_gemm<128><<<g, 128, SMEM128>>>(hptr, eh, el, wh0, wl0, 512, 3072, 96, 0,
                                           nullptr, nullptr, nullptr, nullptr);
    }
    // 3: expand h -> E
    expand_kernel<<<(BATCH * 512 + TB - 1) / TB, TB>>>(hptr, 512);
    // 4: layer1 GEMM (K=6144) -> h   (ncu overall slot #6)
    {
        dim3 g(512 / 128, BATCH / 128);
        kan_gemm<128><<<g, 128, SMEM128>>>(hptr, eh, el, wh1, wl1, 512, 6144, 192, 0,
                                           nullptr, nullptr, nullptr, nullptr);
    }
    // 5: expand h -> E
    expand_kernel<<<(BATCH * 512 + TB - 1) / TB, TB>>>(hptr, 512);
    // 6: layer2 GEMM (K=6144, MT=64 -> 256 CTAs) -> BN -> out
    {
        dim3 g(256 / 128, BATCH / 64);
        kan_gemm<64><<<g, 128, SMEM64>>>(out, eh, el, wh2, wl2, 256, 6144, 192, 1,
                                         bn_gamma, bn_beta, bn_mean, bn_var);
    }
}